// round 11
// baseline (speedup 1.0000x reference)
#include <cuda_runtime.h>
#include <math.h>

#define B_   2
#define T_   2048
#define S_   2048
#define E_   1024
#define H_   16
#define DH_  64
#define SCALE_ 0.125f
#define CLAMP_V 50000.0f
#define NBLK 16              // S_/128 stat blocks per row (pass 1)

// Scratch (device globals: no allocations allowed)
__device__ float  g_Qp[B_ * T_ * E_];
__device__ float  g_Kp[B_ * S_ * E_];
__device__ float  g_Vp[B_ * S_ * E_];
__device__ float  g_ctx[B_ * T_ * E_];
__device__ float2 g_part[(size_t)B_ * H_ * T_ * NBLK];

// ---------------------------------------------------------------------------
__device__ __forceinline__ unsigned smem_u32(const void* p) {
    unsigned r;
    asm("{ .reg .u64 t; cvta.to.shared.u64 t, %1; cvt.u32.u64 %0, t; }"
        : "=r"(r) : "l"(p));
    return r;
}

#define CP16(d, s) \
    asm volatile("cp.async.cg.shared.global [%0], [%1], 16;" :: "r"(d), "l"(s))
#define CP_COMMIT() asm volatile("cp.async.commit_group;" ::: "memory")
#define CP_WAIT(n)  asm volatile("cp.async.wait_group %0;" :: "n"(n) : "memory")

__device__ __forceinline__ unsigned cvt_tf32(float x) {
    unsigned r;
    asm("cvt.rna.tf32.f32 %0, %1;" : "=r"(r) : "f"(x));
    return r;
}
__device__ __forceinline__ float tf32f(float x) {
    return __uint_as_float(cvt_tf32(x));
}

__device__ __forceinline__ void mma8(float* d, const unsigned* a, const unsigned* b) {
    asm volatile(
        "mma.sync.aligned.m16n8k8.row.col.f32.tf32.tf32.f32 "
        "{%0,%1,%2,%3}, {%4,%5,%6,%7}, {%8,%9}, {%0,%1,%2,%3};"
        : "+f"(d[0]), "+f"(d[1]), "+f"(d[2]), "+f"(d[3])
        : "r"(a[0]), "r"(a[1]), "r"(a[2]), "r"(a[3]), "r"(b[0]), "r"(b[1]));
}

__device__ __forceinline__ void softmax_merge(float& m, float& s, float om, float os) {
    float nm = fmaxf(m, om);
    if (nm == -INFINITY) { m = nm; s = 0.f; return; }
    s = s * __expf(m - nm) + os * __expf(om - nm);
    m = nm;
}

struct GemmArgs {
    const float* A[3];
    const float* W[3];
    const float* bias[3];
    float*       C[3];
    float        alpha[3];
};

// ---------------------------------------------------------------------------
// NT GEMM + bias + alpha.  BM=BN=128, BK=32, 256 thr, 8 warps (2m x 4n),
// warp tile 64x32.  cp.async 2-stage, raw fp32 dynamic smem [2][128][36] x2.
// ---------------------------------------------------------------------------
#define GS_STRIDE 36
#define GS_BUF    (128 * GS_STRIDE)          // floats per buffer
#define GS_B      (2 * GS_BUF)               // Bs base (floats)
#define GS_TOT    (4 * GS_BUF)               // total floats (73728 B)

__global__ __launch_bounds__(256) void gemm_nt_bias(
    GemmArgs ga, int K, int lda, int ldb, int ldc)
{
    extern __shared__ float gsm[];
    const int z = blockIdx.z;
    const float* A    = ga.A[z];
    const float* Bm   = ga.W[z];
    const float* bias = ga.bias[z];
    float*       C    = ga.C[z];
    const float  alpha = ga.alpha[z];

    const int tid = threadIdx.x;
    const int lane = tid & 31, w = tid >> 5;
    const int wm = w & 1, wn = w >> 1;
    const int lr = lane >> 2, lc = lane & 3;
    const int bm = blockIdx.y * 128, bn = blockIdx.x * 128;
    const int row = tid >> 1, half = tid & 1;

    const float* Ag = A + (size_t)(bm + row) * lda + half * 16;
    const float* Bg = Bm + (size_t)(bn + row) * ldb + half * 16;
    const unsigned daBase = smem_u32(&gsm[row * GS_STRIDE + half * 16]);
    const unsigned dbBase = smem_u32(&gsm[GS_B + row * GS_STRIDE + half * 16]);
    const unsigned bufStride = GS_BUF * 4;

#define G_STAGE(kc, buf)                                                   \
    do {                                                                   \
        unsigned da = daBase + (buf) * bufStride;                          \
        unsigned db = dbBase + (buf) * bufStride;                          \
        _Pragma("unroll")                                                  \
        for (int c = 0; c < 4; c++) {                                      \
            CP16(da + c * 16, Ag + (kc) * 32 + c * 4);                     \
            CP16(db + c * 16, Bg + (kc) * 32 + c * 4);                     \
        }                                                                  \
        CP_COMMIT();                                                       \
    } while (0)

    float acc[4][4][4] = {};

    const int NC = K >> 5;
    G_STAGE(0, 0);
    G_STAGE(1, 1);

    for (int kc = 0; kc < NC; kc++) {
        const int buf = kc & 1;
        if (kc + 1 < NC) CP_WAIT(1); else CP_WAIT(0);
        __syncthreads();
        const float* As_ = gsm + buf * GS_BUF;
        const float* Bs_ = gsm + GS_B + buf * GS_BUF;
#pragma unroll
        for (int kt = 0; kt < 4; kt++) {
            const int kk = kt * 8;
            unsigned af[4][4], bf[4][2];
#pragma unroll
            for (int i = 0; i < 4; i++) {
                int mr = wm * 64 + i * 16 + lr;
                af[i][0] = cvt_tf32(As_[mr * GS_STRIDE + kk + lc]);
                af[i][1] = cvt_tf32(As_[(mr + 8) * GS_STRIDE + kk + lc]);
                af[i][2] = cvt_tf32(As_[mr * GS_STRIDE + kk + 4 + lc]);
                af[i][3] = cvt_tf32(As_[(mr + 8) * GS_STRIDE + kk + 4 + lc]);
            }
#pragma unroll
            for (int j = 0; j < 4; j++) {
                int nr = wn * 32 + j * 8 + lr;
                bf[j][0] = cvt_tf32(Bs_[nr * GS_STRIDE + kk + lc]);
                bf[j][1] = cvt_tf32(Bs_[nr * GS_STRIDE + kk + 4 + lc]);
            }
#pragma unroll
            for (int i = 0; i < 4; i++)
#pragma unroll
                for (int j = 0; j < 4; j++)
                    mma8(acc[i][j], af[i], bf[j]);
        }
        __syncthreads();
        if (kc + 2 < NC) G_STAGE(kc + 2, buf);
    }
#undef G_STAGE

#pragma unroll
    for (int j = 0; j < 4; j++) {
        int col = bn + wn * 32 + j * 8 + lc * 2;
        float b0v = bias[col], b1v = bias[col + 1];
#pragma unroll
        for (int i = 0; i < 4; i++) {
            int r0 = bm + wm * 64 + i * 16 + lr;
            *(float2*)(C + (size_t)r0 * ldc + col) =
                make_float2(alpha * (acc[i][j][0] + b0v), alpha * (acc[i][j][1] + b1v));
            *(float2*)(C + (size_t)(r0 + 8) * ldc + col) =
                make_float2(alpha * (acc[i][j][2] + b0v), alpha * (acc[i][j][3] + b1v));
        }
    }
}

// ---------------------------------------------------------------------------
// Pass 1 — stats only (unchanged from R10): per (b,h) 128x128 tile,
// emits per-(row, block) (m, s) to part.  No score stores.
// ---------------------------------------------------------------------------
#define K8_RAW(As_, Bs_, kk, mbase, nbase, acc)                            \
    do {                                                                   \
        unsigned af[4][4], bf[4][2];                                       \
        _Pragma("unroll")                                                  \
        for (int i = 0; i < 4; i++) {                                      \
            int mr = (mbase) + i * 16 + lr;                                \
            af[i][0] = cvt_tf32((As_)[mr][(kk) + lc]);                     \
            af[i][1] = cvt_tf32((As_)[mr + 8][(kk) + lc]);                 \
            af[i][2] = cvt_tf32((As_)[mr][(kk) + 4 + lc]);                 \
            af[i][3] = cvt_tf32((As_)[mr + 8][(kk) + 4 + lc]);             \
        }                                                                  \
        _Pragma("unroll")                                                  \
        for (int j = 0; j < 4; j++) {                                      \
            int nr = (nbase) + j * 8 + lr;                                 \
            bf[j][0] = cvt_tf32((Bs_)[nr][(kk) + lc]);                     \
            bf[j][1] = cvt_tf32((Bs_)[nr][(kk) + 4 + lc]);                 \
        }                                                                  \
        _Pragma("unroll")                                                  \
        for (int i = 0; i < 4; i++)                                        \
            _Pragma("unroll")                                              \
            for (int j = 0; j < 4; j++)                                    \
                mma8(acc[i][j], af[i], bf[j]);                             \
    } while (0)

__global__ __launch_bounds__(256) void attn_stats(
    const float* __restrict__ Qp, const float* __restrict__ Kp,
    const int* __restrict__ mask, float2* __restrict__ part)
{
    __shared__ float As[2][128][20];
    __shared__ float Bs[2][128][20];
    __shared__ float red_m[4][128];
    __shared__ float red_s[4][128];
    __shared__ int msk[128];

    const int bh = blockIdx.z, b = bh >> 4, h = bh & 15;

    const int tid = threadIdx.x;
    const int lane = tid & 31, w = tid >> 5;
    const int wm = w & 1, wn = w >> 1;
    const int lr = lane >> 2, lc = lane & 3;
    const int bm = blockIdx.y * 128, bn = blockIdx.x * 128;
    const int row = tid >> 1, half = tid & 1;

    const float* Ag = Qp + (size_t)b * T_ * E_ + (size_t)(bm + row) * E_ + h * DH_ + half * 8;
    const float* Bg = Kp + (size_t)b * S_ * E_ + (size_t)(bn + row) * E_ + h * DH_ + half * 8;
    const unsigned daBase = smem_u32(&As[0][row][half * 8]);
    const unsigned dbBase = smem_u32(&Bs[0][row][half * 8]);
    const unsigned bufStride = 128 * 20 * 4;

#define S_STAGE(kc, buf)                                                   \
    do {                                                                   \
        unsigned da = daBase + (buf) * bufStride;                          \
        unsigned db = dbBase + (buf) * bufStride;                          \
        CP16(da,      Ag + (kc) * 16);                                     \
        CP16(da + 16, Ag + (kc) * 16 + 4);                                 \
        CP16(db,      Bg + (kc) * 16);                                     \
        CP16(db + 16, Bg + (kc) * 16 + 4);                                 \
        CP_COMMIT();                                                       \
    } while (0)

    if (tid < 128) msk[tid] = mask[(size_t)b * S_ + bn + tid];

    float acc[4][4][4] = {};

    S_STAGE(0, 0);
    S_STAGE(1, 1);

#pragma unroll
    for (int kc = 0; kc < 4; kc++) {
        const int buf = kc & 1;
        if (kc < 3) CP_WAIT(1); else CP_WAIT(0);
        __syncthreads();
        K8_RAW(As[buf], Bs[buf], 0, wm * 64, wn * 32, acc);
        K8_RAW(As[buf], Bs[buf], 8, wm * 64, wn * 32, acc);
        __syncthreads();
        if (kc < 2) S_STAGE(kc + 2, buf);
    }
#undef S_STAGE

#define SCV(i, j, idx, keep) \
    ((keep) ? fminf(fmaxf(acc[i][j][idx], -CLAMP_V), CLAMP_V) : -INFINITY)

#pragma unroll
    for (int i = 0; i < 4; i++) {
        int rl = wm * 64 + i * 16 + lr;
        float m_lo = -INFINITY, m_hi = -INFINITY;
#pragma unroll
        for (int j = 0; j < 4; j++) {
            int lcol = wn * 32 + j * 8 + lc * 2;
            bool k0 = msk[lcol] != 0, k1 = msk[lcol + 1] != 0;
            m_lo = fmaxf(m_lo, fmaxf(SCV(i, j, 0, k0), SCV(i, j, 1, k1)));
            m_hi = fmaxf(m_hi, fmaxf(SCV(i, j, 2, k0), SCV(i, j, 3, k1)));
        }
#pragma unroll
        for (int off = 1; off <= 2; off <<= 1) {
            m_lo = fmaxf(m_lo, __shfl_xor_sync(0xffffffffu, m_lo, off));
            m_hi = fmaxf(m_hi, __shfl_xor_sync(0xffffffffu, m_hi, off));
        }
        if (lc == 0) {
            red_m[wn][rl]     = m_lo;
            red_m[wn][rl + 8] = m_hi;
        }
    }
    __syncthreads();

#pragma unroll
    for (int i = 0; i < 4; i++) {
        int rl = wm * 64 + i * 16 + lr;
        float mlo = fmaxf(fmaxf(red_m[0][rl], red_m[1][rl]),
                          fmaxf(red_m[2][rl], red_m[3][rl]));
        float mhi = fmaxf(fmaxf(red_m[0][rl + 8], red_m[1][rl + 8]),
                          fmaxf(red_m[2][rl + 8], red_m[3][rl + 8]));
        float mlou = (mlo == -INFINITY) ? 0.f : mlo;
        float mhiu = (mhi == -INFINITY) ? 0.f : mhi;
        float s_lo = 0.f, s_hi = 0.f;
#pragma unroll
        for (int j = 0; j < 4; j++) {
            int lcol = wn * 32 + j * 8 + lc * 2;
            bool k0 = msk[lcol] != 0, k1 = msk[lcol + 1] != 0;
            s_lo += __expf(SCV(i, j, 0, k0) - mlou) + __expf(SCV(i, j, 1, k1) - mlou);
            s_hi += __expf(SCV(i, j, 2, k0) - mhiu) + __expf(SCV(i, j, 3, k1) - mhiu);
        }
#pragma unroll
        for (int off = 1; off <= 2; off <<= 1) {
            s_lo += __shfl_xor_sync(0xffffffffu, s_lo, off);
            s_hi += __shfl_xor_sync(0xffffffffu, s_hi, off);
        }
        if (lc == 0) {
            red_s[wn][rl]     = s_lo;
            red_s[wn][rl + 8] = s_hi;
        }
    }
    __syncthreads();

    if (tid < 128) {
        float m = fmaxf(fmaxf(red_m[0][tid], red_m[1][tid]),
                        fmaxf(red_m[2][tid], red_m[3][tid]));
        float s = red_s[0][tid] + red_s[1][tid] + red_s[2][tid] + red_s[3][tid];
        part[((size_t)bh * T_ + bm + tid) * NBLK + blockIdx.x] = make_float2(m, s);
    }
#undef SCV
}

// ---------------------------------------------------------------------------
// Pass 2 — fused: recompute QK^T per 64-col block (full K block staged once),
// p = exp(clamp(v) - m_glob)*inv (mask->0), write p to attn ONCE, Ps smem
// bounce, Ctx += P @ V.  3 syncs per col-block; next K prefetched behind PV.
// Layout (floats): Q[128][68] | Ps[64][136] | K[64][68] | V[64][72] |
//                  st float2[128] | mk char[2048]
// ---------------------------------------------------------------------------
#define FZ_Q  0
#define FZ_P  8704
#define FZ_K  17408
#define FZ_V  21760
#define FZ_ST 26368
#define FZ_MK 26624
#define FZ_TOT 27136

__global__ __launch_bounds__(256, 2) void attn_fused(
    const float* __restrict__ Qp, const float* __restrict__ Kp,
    const float* __restrict__ Vp, const int* __restrict__ mask,
    const float2* __restrict__ part, float* __restrict__ P,
    float* __restrict__ Ctx)
{
    extern __shared__ float sm[];
    const int bh = blockIdx.y, b = bh >> 4, h = bh & 15;
    const int tid = threadIdx.x;
    const int lane = tid & 31, w = tid >> 5;
    const int wm = w & 1, wn = w >> 1;
    const int lr = lane >> 2, lc = lane & 3;
    const int bm = blockIdx.x * 128;
    const unsigned smb = smem_u32(sm);

    const int srow = tid >> 4, sseg = tid & 15;   // 16 rows x 16 segs loaders

    // row stats: merge 16 block partials -> (m_glob, 1/s)
    if (tid < 128) {
        float m = -INFINITY, s = 0.f;
#pragma unroll
        for (int j = 0; j < NBLK; j++) {
            float2 p = part[((size_t)bh * T_ + bm + tid) * NBLK + j];
            softmax_merge(m, s, p.x, p.y);
        }
        ((float2*)(sm + FZ_ST))[tid] = make_float2(m, 1.f / s);
    }
    // mask bytes for all S
    {
        char* mk = (char*)(sm + FZ_MK);
        const int* mg = mask + (size_t)b * S_;
#pragma unroll
        for (int u = 0; u < 8; u++) {
            int i = u * 256 + tid;
            mk[i] = (mg[i] != 0);
        }
    }

    const float* Kg = Kp + (size_t)b * S_ * E_ + h * DH_;
    const float* Vg = Vp + (size_t)b * S_ * E_ + h * DH_;

#define STAGE_K(cb)                                                        \
    do {                                                                   \
        _Pragma("unroll")                                                  \
        for (int u = 0; u < 4; u++) {                                      \
            int lin = u * 256 + tid;                                       \
            int r_ = lin >> 4, sg = lin & 15;                              \
            CP16(smb + (FZ_K + r_ * 68 + sg * 4) * 4,                      \
                 Kg + (size_t)((cb) * 64 + r_) * E_ + sg * 4);             \
        }                                                                  \
        CP_COMMIT();                                                       \
    } while (0)

#define STAGE_V(cb)                                                        \
    do {                                                                   \
        _Pragma("unroll")                                                  \
        for (int u = 0; u < 4; u++) {                                      \
            int lin = u * 256 + tid;                                       \
            int r_ = lin >> 4, sg = lin & 15;                              \
            CP16(smb + (FZ_V + r_ * 72 + sg * 4) * 4,                      \
                 Vg + (size_t)((cb) * 64 + r_) * E_ + sg * 4);             \
        }                                                                  \
        CP_COMMIT();                                                       \
    } while (0)

    // stage Q (rows bm..bm+127, 64 k) raw row-major [128][68]
    {
        const float* Qg = Qp + (size_t)b * T_ * E_ + (size_t)bm * E_ + h * DH_;
#pragma unroll
        for (int u = 0; u < 8; u++) {
            int lin = u * 256 + tid;
            int r_ = lin >> 4, sg = lin & 15;
            CP16(smb + (FZ_Q + r_ * 68 + sg * 4) * 4,
                 Qg + (size_t)r_ * E_ + sg * 4);
        }
        CP_COMMIT();
    }
    STAGE_K(0);
    STAGE_V(0);

    float* Pg = P + (size_t)bh * T_ * S_;
    const float2* st = (const float2*)(sm + FZ_ST);
    const char* mk = (const char*)(sm + FZ_MK);

    float acc_c[4][2][4] = {};

    for (int cb = 0; cb < 32; cb++) {
        CP_WAIT(0);
        __syncthreads();   // Q(first), K(cb), V(cb), stats, mask all visible

        // scores: 8 k8 steps, K=64 resident
        float acc_s[4][2][4] = {};
        {
            const float* Qb = sm + FZ_Q;
            const float* Kb = sm + FZ_K;
#pragma unroll
            for (int kt = 0; kt < 8; kt++) {
                const int kk = kt * 8;
                unsigned af[4][4], bf[2][2];
#pragma unroll
                for (int i = 0; i < 4; i++) {
                    int mr = wm * 64 + i * 16 + lr;
                    af[i][0] = cvt_tf32(Qb[mr * 68 + kk + lc]);
                    af[i][1] = cvt_tf32(Qb[(mr + 8) * 68 + kk + lc]);
                    af[i][2] = cvt_tf32(Qb[mr * 68 + kk + 4 + lc]);
                    af[i][3] = cvt_tf32(Qb[(mr + 8) * 68 + kk + 4 + lc]);
                }
#pragma unroll
                for (int j = 0; j < 2; j++) {
                    int nb = wn * 16 + j * 8 + lr;
                    bf[j][0] = cvt_tf32(Kb[nb * 68 + kk + lc]);
                    bf[j][1] = cvt_tf32(Kb[nb * 68 + kk + 4 + lc]);
                }
#pragma unroll
                for (int i = 0; i < 4; i++)
#pragma unroll
                    for (int j = 0; j < 2; j++)
                        mma8(acc_s[i][j], af[i], bf[j]);
            }
        }

        // epilogue: p = exp(clamp(v)-m)*inv (mask->0); write attn + Ps smem
        {
            float* Pb = sm + FZ_P;
#pragma unroll
            for (int i = 0; i < 4; i++) {
                int rl = wm * 64 + i * 16 + lr;
                float2 s0 = st[rl], s1 = st[rl + 8];
                float m0 = (s0.x == -INFINITY) ? 0.f : s0.x;
                float m1 = (s1.x == -INFINITY) ? 0.f : s1.x;
#pragma unroll
                for (int j = 0; j < 2; j++) {
                    int lcol = wn * 16 + j * 8 + lc * 2;
                    int gcol = cb * 64 + lcol;
                    bool k0 = mk[gcol] != 0, k1 = mk[gcol + 1] != 0;
                    float v00 = fminf(fmaxf(acc_s[i][j][0], -CLAMP_V), CLAMP_V);
                    float v01 = fminf(fmaxf(acc_s[i][j][1], -CLAMP_V), CLAMP_V);
                    float v10 = fminf(fmaxf(acc_s[i][j][2], -CLAMP_V), CLAMP_V);
                    float v11 = fminf(fmaxf(acc_s[i][j][3], -CLAMP_V), CLAMP_V);
                    float p00 = k0 ? __expf(v00 - m0) * s0.y : 0.f;
                    float p01 = k1 ? __expf(v01 - m0) * s0.y : 0.f;
                    float p10 = k0 ? __expf(v10 - m1) * s1.y : 0.f;
                    float p11 = k1 ? __expf(v11 - m1) * s1.y : 0.f;
                    *(float2*)(Pg + (size_t)(bm + rl) * S_ + gcol)     = make_float2(p00, p01);
                    *(float2*)(Pg + (size_t)(bm + rl + 8) * S_ + gcol) = make_float2(p10, p11);
                    Pb[lcol * 136 + rl]           = tf32f(p00);
                    Pb[(lcol + 1) * 136 + rl]     = tf32f(p01);
                    Pb[lcol * 136 + rl + 8]       = tf32f(p10);
                    Pb[(lcol + 1) * 136 + rl + 8] = tf32f(p11);
                }
            }
        }
        __syncthreads();   // Ps ready; K region dead

        // prefetch next K behind PV
        if (cb + 1 < 32) STAGE_K(cb + 1);

        // PV: Ctx += P(128x64) @ V(64x64)
        {
            const float* Pb = sm + FZ_P;
            const float* Vb = sm + FZ_V;
#pragma unroll
            for (int kt8 = 0; kt8 < 8; kt8++) {
                const int kk = kt8 * 8;
                unsigned af[4][4], bf[2][2];
#pragma unroll
                for (int i = 0; i < 4; i++) {
                    int mb = wm * 64 + i * 16 + lr;
                    af[i][0] = __float_as_uint(Pb[(kk + lc) * 136 + mb]);
                    af[i][1] = __float_as_uint(Pb[(kk + lc) * 136 + mb + 8]);
                    af[i][2] = __float_as_uint(Pb[(kk + 4 + lc) * 136 + mb]);
                    af[i][3] = __float_as_uint(Pb[(kk + 4 + lc) * 136 + mb + 8]);
                }
#pragma unroll
                for (int j = 0; j < 2; j++) {
                    int nb = wn * 16 + j * 8 + lr;
                    bf[j][0] = cvt_tf32(Vb[(kk + lc) * 72 + nb]);
                    bf[j][1] = cvt_tf32(Vb[(kk + 4 + lc) * 72 + nb]);
                }
#pragma unroll
                for (int i = 0; i < 4; i++)
#pragma unroll
                    for (int j = 0; j < 2; j++)
                        mma8(acc_c[i][j], af[i], bf[j]);
            }
        }
        __syncthreads();   // V, Ps free

        if (cb + 1 < 32) STAGE_V(cb + 1);
    }
#undef STAGE_K
#undef STAGE_V

    // Ctx epilogue
    {
        float* Cg = Ctx + (size_t)b * T_ * E_ + h * DH_;
#pragma unroll
        for (int j = 0; j < 2; j++) {
            int col = wn * 16 + j * 8 + lc * 2;
#pragma unroll
            for (int i = 0; i < 4; i++) {
                int r0 = bm + wm * 64 + i * 16 + lr;
                *(float2*)(Cg + (size_t)r0 * E_ + col) =
                    make_float2(acc_c[i][j][0], acc_c[i][j][1]);
                *(float2*)(Cg + (size_t)(r0 + 8) * E_ + col) =
                    make_float2(acc_c[i][j][2], acc_c[i][j][3]);
            }
        }
    }
}

// ---------------------------------------------------------------------------
extern "C" void kernel_launch(void* const* d_in, const int* in_sizes, int n_in,
                              void* d_out, int out_size)
{
    const float* q    = (const float*)d_in[0];
    const float* k    = (const float*)d_in[1];
    const float* v    = (const float*)d_in[2];
    const int*   mask = (const int*)d_in[3];
    const float* Wq   = (const float*)d_in[4];
    const float* bq   = (const float*)d_in[5];
    const float* Wk   = (const float*)d_in[6];
    const float* bk   = (const float*)d_in[7];
    const float* Wv   = (const float*)d_in[8];
    const float* bv   = (const float*)d_in[9];
    const float* Wo   = (const float*)d_in[10];
    const float* bo   = (const float*)d_in[11];

    float* out  = (float*)d_out;
    float* attn = out + (size_t)B_ * T_ * E_;

    float *Qp, *Kp, *Vp, *Ctx;
    float2 *part;
    cudaGetSymbolAddress((void**)&Qp, g_Qp);
    cudaGetSymbolAddress((void**)&Kp, g_Kp);
    cudaGetSymbolAddress((void**)&Vp, g_Vp);
    cudaGetSymbolAddress((void**)&Ctx, g_ctx);
    cudaGetSymbolAddress((void**)&part, g_part);

    cudaFuncSetAttribute(gemm_nt_bias,
                         cudaFuncAttributeMaxDynamicSharedMemorySize,
                         GS_TOT * 4);
    cudaFuncSetAttribute(attn_fused,
                         cudaFuncAttributeMaxDynamicSharedMemorySize,
                         FZ_TOT * 4);

    dim3 gq(E_ / 128, (B_ * T_) / 128, 3);   // QKV fused: (8, 32, 3)
    GemmArgs g1;
    g1.A[0] = q;  g1.W[0] = Wq; g1.bias[0] = bq; g1.C[0] = Qp; g1.alpha[0] = SCALE_;
    g1.A[1] = k;  g1.W[1] = Wk; g1.bias[1] = bk; g1.C[1] = Kp; g1.alpha[1] = 1.0f;
    g1.A[2] = v;  g1.W[2] = Wv; g1.bias[2] = bv; g1.C[2] = Vp; g1.alpha[2] = 1.0f;
    gemm_nt_bias<<<gq, 256, GS_TOT * 4>>>(g1, E_, E_, E_, E_);

    attn_stats<<<dim3(S_ / 128, T_ / 128, B_ * H_), 256>>>(Qp, Kp, mask, part);

    attn_fused<<<dim3(T_ / 128, B_ * H_), 256, FZ_TOT * 4>>>(
        Qp, Kp, Vp, mask, part, attn, Ctx);

    GemmArgs g2;
    g2.A[0] = Ctx; g2.W[0] = Wo; g2.bias[0] = bo; g2.C[0] = out; g2.alpha[0] = 1.0f;
    g2.A[1] = Ctx; g2.W[1] = Wo; g2.bias[1] = bo; g2.C[1] = out; g2.alpha[1] = 1.0f;
    g2.A[2] = Ctx; g2.W[2] = Wo; g2.bias[2] = bo; g2.C[2] = out; g2.alpha[2] = 1.0f;
    gemm_nt_bias<<<dim3(E_ / 128, (B_ * T_) / 128, 1), 256, GS_TOT * 4>>>(g2, E_, E_, E_, E_);
}